// round 1
// baseline (speedup 1.0000x reference)
#include <cuda_runtime.h>
#include <cuda_fp16.h>
#include <cstdint>

// LocallyConnected2D: B=64, H=W=32, C=64, KH=KW=3, stride 1 -> oR=oC=30, P=900
// out[b,p,o] = relu( sum_f patches[b,p,f] * kernel[p,f,o] + bias[p,o] )
// Per CTA: one position p. A = patches (64x576) fp16 in smem,
// W^T fp16 swizzled in smem, mma.sync m16n8k16 fp32-accum.

#define BATCH   64
#define PDIM    900
#define KDIM    576
#define ODIM    64
#define OUT_BSTRIDE (PDIM * ODIM)   // 57600
#define A_STRIDE 584                 // halves per A row (292 words; 292 % 32 == 4)
#define A_BYTES (BATCH * A_STRIDE * 2)        // 74752
#define W_WORDS (ODIM * 292)                  // 18688 words (74752 B)
#define SMEM_BYTES (A_BYTES + W_WORDS * 4)    // 149504

__global__ void __launch_bounds__(256, 1)
lc2d_kernel(const float* __restrict__ x,
            const float* __restrict__ kern,
            const float* __restrict__ bias,
            float* __restrict__ out)
{
    const int p = blockIdx.x;          // 0..899
    const int rr = p / 30;
    const int cc = p - rr * 30;

    extern __shared__ char smem[];
    __half*   As = (__half*)smem;                     // [64][A_STRIDE]
    uint32_t* Ws = (uint32_t*)(smem + A_BYTES);       // swizzled half2 words

    const int tid = threadIdx.x;

    // ---------------- Load A: patches (64 x 576) fp32 -> fp16 ----------------
    // 576 segments (b,k9) of 64 contiguous channel floats; 16 threads/segment.
    {
        const int lane16 = tid & 15;
        for (int seg = tid >> 4; seg < BATCH * 9; seg += 16) {
            const int b  = seg / 9;
            const int k9 = seg - b * 9;
            const int di = k9 / 3;
            const int dj = k9 - di * 3;
            const float4 v = *(const float4*)(x +
                (((b * 32 + rr + di) * 32) + (cc + dj)) * 64 + lane16 * 4);
            __half2 h0 = __floats2half2_rn(v.x, v.y);
            __half2 h1 = __floats2half2_rn(v.z, v.w);
            uint32_t u0 = *(uint32_t*)&h0;
            uint32_t u1 = *(uint32_t*)&h1;
            uint2* dst = (uint2*)(As + b * A_STRIDE + k9 * 64 + lane16 * 4);
            *dst = make_uint2(u0, u1);
        }
    }

    // ------------- Load W (576 x 64) -> transposed + swizzled fp16 -----------
    // thread owns column o = tid&63; iterates f-pairs. Store word index:
    //   idx(o, e) = o*292 + (e ^ ((o>>3)&3)),  e = f/2
    // -> conflict-free stores (lanes vary o) and conflict-free B-frag reads.
    {
        const int o  = tid & 63;
        const int sw = (o >> 3) & 3;
        const float* wp = kern + (size_t)p * (KDIM * ODIM) + o;
        uint32_t* wrow = Ws + o * 292;
        for (int e = tid >> 6; e < KDIM / 2; e += 4) {
            const float w0 = wp[(2 * e) * 64];
            const float w1 = wp[(2 * e + 1) * 64];
            __half2 h = __floats2half2_rn(w0, w1);
            wrow[e ^ sw] = *(uint32_t*)&h;
        }
    }

    __syncthreads();

    // ---------------- Compute: 8 warps, each 16 rows x 32 cols ---------------
    const int w    = tid >> 5;
    const int lane = tid & 31;
    const int g    = lane >> 2;     // 0..7
    const int t    = lane & 3;      // 0..3
    const int row0 = (w >> 1) * 16; // 0,16,32,48
    const int col0 = (w & 1) * 32;  // 0,32

    float acc[4][4];
    #pragma unroll
    for (int nt = 0; nt < 4; nt++)
        #pragma unroll
        for (int i = 0; i < 4; i++) acc[nt][i] = 0.f;

    const __half* arow0 = As + (row0 + g)     * A_STRIDE + 2 * t;
    const __half* arow1 = As + (row0 + g + 8) * A_STRIDE + 2 * t;

    #pragma unroll 4
    for (int kb = 0; kb < KDIM; kb += 16) {
        uint32_t a0 = *(const uint32_t*)(arow0 + kb);
        uint32_t a1 = *(const uint32_t*)(arow1 + kb);
        uint32_t a2 = *(const uint32_t*)(arow0 + kb + 8);
        uint32_t a3 = *(const uint32_t*)(arow1 + kb + 8);
        const int ebase = (kb >> 1) + t;
        #pragma unroll
        for (int nt = 0; nt < 4; nt++) {
            const int o  = col0 + nt * 8 + g;
            const int sw = (o >> 3) & 3;
            const uint32_t* wrow = Ws + o * 292;
            uint32_t b0 = wrow[ebase ^ sw];
            uint32_t b1 = wrow[(ebase + 4) ^ sw];
            asm volatile(
                "mma.sync.aligned.m16n8k16.row.col.f32.f16.f16.f32 "
                "{%0,%1,%2,%3}, {%4,%5,%6,%7}, {%8,%9}, {%0,%1,%2,%3};\n"
                : "+f"(acc[nt][0]), "+f"(acc[nt][1]),
                  "+f"(acc[nt][2]), "+f"(acc[nt][3])
                : "r"(a0), "r"(a1), "r"(a2), "r"(a3), "r"(b0), "r"(b1));
        }
    }

    // ---------------- Epilogue: bias + ReLU + store --------------------------
    const float* bp = bias + p * ODIM;
    float* op = out + p * ODIM;
    const int r0i = row0 + g;
    const int r1i = row0 + g + 8;
    #pragma unroll
    for (int nt = 0; nt < 4; nt++) {
        const int o = col0 + nt * 8 + 2 * t;
        const float bv0 = bp[o];
        const float bv1 = bp[o + 1];
        float2 v0 = make_float2(fmaxf(acc[nt][0] + bv0, 0.f),
                                fmaxf(acc[nt][1] + bv1, 0.f));
        float2 v1 = make_float2(fmaxf(acc[nt][2] + bv0, 0.f),
                                fmaxf(acc[nt][3] + bv1, 0.f));
        *(float2*)(op + (size_t)r0i * OUT_BSTRIDE + o) = v0;
        *(float2*)(op + (size_t)r1i * OUT_BSTRIDE + o) = v1;
    }
}

extern "C" void kernel_launch(void* const* d_in, const int* in_sizes, int n_in,
                              void* d_out, int out_size)
{
    const float* x    = (const float*)d_in[0];   // (64,32,32,64)
    const float* kern = (const float*)d_in[1];   // (900,576,64)
    const float* bias = (const float*)d_in[2];   // (30,30,64)
    float* out = (float*)d_out;                  // (64,30,30,64)

    cudaFuncSetAttribute(lc2d_kernel,
                         cudaFuncAttributeMaxDynamicSharedMemorySize,
                         SMEM_BYTES);
    lc2d_kernel<<<PDIM, 256, SMEM_BYTES>>>(x, kern, bias, out);
}

// round 3
// speedup vs baseline: 2.3664x; 2.3664x over previous
#include <cuda_runtime.h>
#include <cstdint>

// LocallyConnected2D B=64,H=W=32,C=64,3x3,s1 -> P=900, K=576, O=64
// Per CTA: position p. tf32 mma m16n8k8, cp.async 3-stage K-pipeline (chunk=64).
// Chunk j == spatial tap (di,dj)=(j/3,j%3): A chunk rows are 256B contiguous in x;
// W chunk is a contiguous 16KB block of kern (64 k-rows x 64 outputs).

#define PDIM  900
#define KDIM  576
#define ODIM  64
#define OB    (PDIM * ODIM)      // out batch stride
#define NCHUNK 9
#define AROW  68                  // fp32 words per A row (64 data + 4 pad)
#define ASTW  (64 * AROW)         // 4352 words
#define WSTW  (64 * 64)           // 4096 words
#define STW   (ASTW + WSTW)       // 8448 words / stage
#define NST   3
#define SMEM_BYTES (STW * NST * 4)   // 101376 B -> 2 CTAs/SM

__device__ __forceinline__ uint32_t s2u(const void* p) {
    uint32_t a;
    asm("{.reg .u64 t; cvta.to.shared.u64 t, %1; cvt.u32.u64 %0, t;}"
        : "=r"(a) : "l"(p));
    return a;
}
__device__ __forceinline__ void cp16(uint32_t dst, const void* src) {
    asm volatile("cp.async.cg.shared.global [%0], [%1], 16;\n"
                 :: "r"(dst), "l"(src));
}
#define CVT_TF32(r) asm("cvt.rna.tf32.f32 %0, %1;" : "=r"(r) : "r"(r))

__global__ void __launch_bounds__(256, 2)
lc2d_tf32(const float* __restrict__ x,
          const float* __restrict__ kern,
          const float* __restrict__ bias,
          float* __restrict__ out)
{
    const int p  = blockIdx.x;
    const int rr = p / 30;
    const int cc = p - rr * 30;

    extern __shared__ float smem[];
    const uint32_t sbase = s2u(smem);
    const int tid = threadIdx.x;

    // -------- cp.async producer coords --------
    const int ab = tid >> 2;      // A row (batch) 0..63
    const int aq = tid & 3;       // quad group 0..3

    auto issue = [&](int j, int st) {
        const int di = j / 3, dj = j - di * 3;
        // A chunk: x[b, rr+di, cc+dj, 0:64] -> smem [b][c], row stride AROW
        const float* asrc = x + (((ab * 32) + rr + di) * 32 + (cc + dj)) * 64;
        const uint32_t adst = sbase + (uint32_t)(st * STW + ab * AROW) * 4u;
        #pragma unroll
        for (int i = 0; i < 4; i++) {
            const int c = (aq + 4 * i) * 4;          // float offset, 16B aligned
            cp16(adst + (uint32_t)c * 4u, asrc + c);
        }
        // W chunk: kern[p, 64j:64j+64, :]: 64x64 floats = 1024 float4.
        // smem word(k,o) = k*64 + (o ^ ((k&3)<<3)), 16B-granular swizzle
        const float* wsrc = kern + (size_t)p * (KDIM * ODIM) + j * 4096;
        const uint32_t wdst = sbase + (uint32_t)(st * STW + ASTW) * 4u;
        #pragma unroll
        for (int i = 0; i < 4; i++) {
            const int v  = tid + 256 * i;            // float4 index 0..1023
            const int k  = v >> 4, o4 = v & 15;      // k 0..63
            const int wd = k * 64 + ((o4 ^ ((k & 3) << 1)) << 2);
            cp16(wdst + (uint32_t)wd * 4u, wsrc + v * 4);
        }
    };

    // prologue: chunks 0..2 -> stages 0..2
    issue(0, 0); asm volatile("cp.async.commit_group;\n" ::: "memory");
    issue(1, 1); asm volatile("cp.async.commit_group;\n" ::: "memory");
    issue(2, 2); asm volatile("cp.async.commit_group;\n" ::: "memory");

    // -------- consumer coords --------
    const int w    = tid >> 5;
    const int lane = tid & 31;
    const int g    = lane >> 2;   // 0..7
    const int t    = lane & 3;    // 0..3
    const int row0 = (w >> 1) * 16;
    const int col0 = (w & 1) * 32;

    float acc[4][4];
    #pragma unroll
    for (int nt = 0; nt < 4; nt++)
        #pragma unroll
        for (int i = 0; i < 4; i++) acc[nt][i] = 0.f;

    // swizzled B column word per nt (k&3 == t for both b0 and b1)
    int oword[4];
    #pragma unroll
    for (int nt = 0; nt < 4; nt++)
        oword[nt] = (col0 + nt * 8 + g) ^ (t << 3);

    #pragma unroll 1
    for (int j = 0; j < NCHUNK; j++) {
        asm volatile("cp.async.wait_group 2;\n" ::: "memory");
        __syncthreads();

        const int st = j % 3;
        const float* Ab  = smem + st * STW;
        const float* Wb  = Ab + ASTW;
        const float* ar0 = Ab + (row0 + g) * AROW + t;
        const float* ar1 = Ab + (row0 + g + 8) * AROW + t;

        #pragma unroll
        for (int ks = 0; ks < 8; ks++) {
            const int kb = ks * 8;
            uint32_t a0 = __float_as_uint(ar0[kb]);
            uint32_t a1 = __float_as_uint(ar1[kb]);
            uint32_t a2 = __float_as_uint(ar0[kb + 4]);
            uint32_t a3 = __float_as_uint(ar1[kb + 4]);
            CVT_TF32(a0); CVT_TF32(a1); CVT_TF32(a2); CVT_TF32(a3);
            const float* wk0 = Wb + (kb + t) * 64;
            const float* wk1 = Wb + (kb + t + 4) * 64;
            #pragma unroll
            for (int nt = 0; nt < 4; nt++) {
                uint32_t b0 = __float_as_uint(wk0[oword[nt]]);
                uint32_t b1 = __float_as_uint(wk1[oword[nt]]);
                CVT_TF32(b0); CVT_TF32(b1);
                asm volatile(
                    "mma.sync.aligned.m16n8k8.row.col.f32.tf32.tf32.f32 "
                    "{%0,%1,%2,%3}, {%4,%5,%6,%7}, {%8,%9}, {%0,%1,%2,%3};\n"
                    : "+f"(acc[nt][0]), "+f"(acc[nt][1]),
                      "+f"(acc[nt][2]), "+f"(acc[nt][3])
                    : "r"(a0), "r"(a1), "r"(a2), "r"(a3), "r"(b0), "r"(b1));
            }
        }

        __syncthreads();
        if (j + 3 < NCHUNK) issue(j + 3, st);
        asm volatile("cp.async.commit_group;\n" ::: "memory");
    }

    // -------- epilogue: bias + ReLU + store --------
    const float* bp = bias + p * ODIM;
    float* op = out + p * ODIM;
    const int r0i = row0 + g;
    const int r1i = row0 + g + 8;
    #pragma unroll
    for (int nt = 0; nt < 4; nt++) {
        const int o = col0 + nt * 8 + 2 * t;
        const float bv0 = bp[o];
        const float bv1 = bp[o + 1];
        float2 v0 = make_float2(fmaxf(acc[nt][0] + bv0, 0.f),
                                fmaxf(acc[nt][1] + bv1, 0.f));
        float2 v1 = make_float2(fmaxf(acc[nt][2] + bv0, 0.f),
                                fmaxf(acc[nt][3] + bv1, 0.f));
        *(float2*)(op + (size_t)r0i * OB + o) = v0;
        *(float2*)(op + (size_t)r1i * OB + o) = v1;
    }
}

extern "C" void kernel_launch(void* const* d_in, const int* in_sizes, int n_in,
                              void* d_out, int out_size)
{
    const float* x    = (const float*)d_in[0];   // (64,32,32,64)
    const float* kern = (const float*)d_in[1];   // (900,576,64)
    const float* bias = (const float*)d_in[2];   // (30,30,64)
    float* out = (float*)d_out;                  // (64,30,30,64)

    cudaFuncSetAttribute(lc2d_tf32,
                         cudaFuncAttributeMaxDynamicSharedMemorySize,
                         SMEM_BYTES);
    lc2d_tf32<<<PDIM, 256, SMEM_BYTES>>>(x, kern, bias, out);
}

// round 4
// speedup vs baseline: 2.4746x; 1.0457x over previous
#include <cuda_runtime.h>
#include <cstdint>

// LocallyConnected2D B=64,H=W=32,C=64,3x3,s1 -> P=900, K=576, O=64
// Per CTA: position p. tf32 mma m16n8k8, cp.async 2-stage K-pipeline (chunk=64),
// 3 CTAs/SM. Chunk j == tap (di,dj): A rows 256B contiguous in x; W chunk is a
// contiguous 16KB block of kern (64 k-rows x 64 outputs).

#define PDIM  900
#define KDIM  576
#define ODIM  64
#define OB    (PDIM * ODIM)      // out batch stride
#define NCHUNK 9
#define AROW  68                  // fp32 words per A row (64 data + 4 pad)
#define ASTW  (64 * AROW)         // 4352 words
#define WSTW  (64 * 64)           // 4096 words
#define STW   (ASTW + WSTW)       // 8448 words / stage
#define NST   2
#define SMEM_BYTES (STW * NST * 4)   // 67584 B -> 3 CTAs/SM

__device__ __forceinline__ uint32_t s2u(const void* p) {
    uint32_t a;
    asm("{.reg .u64 t; cvta.to.shared.u64 t, %1; cvt.u32.u64 %0, t;}"
        : "=r"(a) : "l"(p));
    return a;
}
__device__ __forceinline__ void cp16(uint32_t dst, const void* src) {
    asm volatile("cp.async.cg.shared.global [%0], [%1], 16;\n"
                 :: "r"(dst), "l"(src));
}
#define CVT_TF32(r) asm("cvt.rna.tf32.f32 %0, %1;" : "=r"(r) : "r"(r))

__global__ void __launch_bounds__(256, 3)
lc2d_tf32(const float* __restrict__ x,
          const float* __restrict__ kern,
          const float* __restrict__ bias,
          float* __restrict__ out)
{
    const int p  = blockIdx.x;
    const int rr = p / 30;
    const int cc = p - rr * 30;

    extern __shared__ float smem[];
    const uint32_t sbase = s2u(smem);
    const int tid = threadIdx.x;

    // -------- cp.async producer coords --------
    const int ab = tid >> 2;      // A row (batch) 0..63
    const int aq = tid & 3;       // quad group 0..3

    auto issue = [&](int j, int st) {
        const int di = j / 3, dj = j - di * 3;
        // A chunk: x[b, rr+di, cc+dj, 0:64] -> smem [b][c], row stride AROW
        const float* asrc = x + (((ab * 32) + rr + di) * 32 + (cc + dj)) * 64;
        const uint32_t adst = sbase + (uint32_t)(st * STW + ab * AROW) * 4u;
        #pragma unroll
        for (int i = 0; i < 4; i++) {
            const int c = (aq + 4 * i) * 4;          // float offset, 16B aligned
            cp16(adst + (uint32_t)c * 4u, asrc + c);
        }
        // W chunk: kern[p, 64j:64j+64, :]: 64x64 floats = 1024 float4.
        // smem word(k,o) = k*64 + (o ^ ((k&3)<<3)), 16B-granular swizzle
        const float* wsrc = kern + (size_t)p * (KDIM * ODIM) + j * 4096;
        const uint32_t wdst = sbase + (uint32_t)(st * STW + ASTW) * 4u;
        #pragma unroll
        for (int i = 0; i < 4; i++) {
            const int v  = tid + 256 * i;            // float4 index 0..1023
            const int k  = v >> 4, o4 = v & 15;      // k 0..63
            const int wd = k * 64 + ((o4 ^ ((k & 3) << 1)) << 2);
            cp16(wdst + (uint32_t)wd * 4u, wsrc + v * 4);
        }
    };

    // prologue: chunks 0,1 -> stages 0,1
    issue(0, 0); asm volatile("cp.async.commit_group;\n" ::: "memory");
    issue(1, 1); asm volatile("cp.async.commit_group;\n" ::: "memory");

    // -------- consumer coords --------
    const int w    = tid >> 5;
    const int lane = tid & 31;
    const int g    = lane >> 2;   // 0..7
    const int t    = lane & 3;    // 0..3
    const int row0 = (w >> 1) * 16;
    const int col0 = (w & 1) * 32;

    float acc[4][4];
    #pragma unroll
    for (int nt = 0; nt < 4; nt++)
        #pragma unroll
        for (int i = 0; i < 4; i++) acc[nt][i] = 0.f;

    // swizzled B column word per nt (k&3 == t for both b0 and b1)
    int oword[4];
    #pragma unroll
    for (int nt = 0; nt < 4; nt++)
        oword[nt] = (col0 + nt * 8 + g) ^ (t << 3);

    #pragma unroll 1
    for (int j = 0; j < NCHUNK; j++) {
        asm volatile("cp.async.wait_group 1;\n" ::: "memory");
        __syncthreads();

        const int st = j & 1;
        const float* Ab  = smem + st * STW;
        const float* Wb  = Ab + ASTW;
        const float* ar0 = Ab + (row0 + g) * AROW + t;
        const float* ar1 = Ab + (row0 + g + 8) * AROW + t;

        #pragma unroll
        for (int ks = 0; ks < 8; ks++) {
            const int kb = ks * 8;
            uint32_t a0 = __float_as_uint(ar0[kb]);
            uint32_t a1 = __float_as_uint(ar1[kb]);
            uint32_t a2 = __float_as_uint(ar0[kb + 4]);
            uint32_t a3 = __float_as_uint(ar1[kb + 4]);
            CVT_TF32(a0); CVT_TF32(a1); CVT_TF32(a2); CVT_TF32(a3);
            const float* wk0 = Wb + (kb + t) * 64;
            const float* wk1 = Wb + (kb + t + 4) * 64;
            #pragma unroll
            for (int nt = 0; nt < 4; nt++) {
                uint32_t b0 = __float_as_uint(wk0[oword[nt]]);
                uint32_t b1 = __float_as_uint(wk1[oword[nt]]);
                CVT_TF32(b0); CVT_TF32(b1);
                asm volatile(
                    "mma.sync.aligned.m16n8k8.row.col.f32.tf32.tf32.f32 "
                    "{%0,%1,%2,%3}, {%4,%5,%6,%7}, {%8,%9}, {%0,%1,%2,%3};\n"
                    : "+f"(acc[nt][0]), "+f"(acc[nt][1]),
                      "+f"(acc[nt][2]), "+f"(acc[nt][3])
                    : "r"(a0), "r"(a1), "r"(a2), "r"(a3), "r"(b0), "r"(b1));
            }
        }

        __syncthreads();
        if (j + 2 < NCHUNK) issue(j + 2, st);
        asm volatile("cp.async.commit_group;\n" ::: "memory");
    }

    // -------- epilogue: bias + ReLU + store --------
    const float* bp = bias + p * ODIM;
    float* op = out + p * ODIM;
    const int r0i = row0 + g;
    const int r1i = row0 + g + 8;
    #pragma unroll
    for (int nt = 0; nt < 4; nt++) {
        const int o = col0 + nt * 8 + 2 * t;
        const float bv0 = bp[o];
        const float bv1 = bp[o + 1];
        float2 v0 = make_float2(fmaxf(acc[nt][0] + bv0, 0.f),
                                fmaxf(acc[nt][1] + bv1, 0.f));
        float2 v1 = make_float2(fmaxf(acc[nt][2] + bv0, 0.f),
                                fmaxf(acc[nt][3] + bv1, 0.f));
        *(float2*)(op + (size_t)r0i * OB + o) = v0;
        *(float2*)(op + (size_t)r1i * OB + o) = v1;
    }
}

extern "C" void kernel_launch(void* const* d_in, const int* in_sizes, int n_in,
                              void* d_out, int out_size)
{
    const float* x    = (const float*)d_in[0];   // (64,32,32,64)
    const float* kern = (const float*)d_in[1];   // (900,576,64)
    const float* bias = (const float*)d_in[2];   // (30,30,64)
    float* out = (float*)d_out;                  // (64,30,30,64)

    cudaFuncSetAttribute(lc2d_tf32,
                         cudaFuncAttributeMaxDynamicSharedMemorySize,
                         SMEM_BYTES);
    lc2d_tf32<<<PDIM, 256, SMEM_BYTES>>>(x, kern, bias, out);
}